// round 4
// baseline (speedup 1.0000x reference)
#include <cuda_runtime.h>
#include <math.h>
#include <stdint.h>

#define T_TOK 2048
#define DIM   1024
#define NEXP  8
#define FF    512
#define FSH   1024

// ---------------- scratch (__device__ globals: allocation-free) ----------------
__device__ int   g_count[NEXP];
__device__ int   g_tok[NEXP][T_TOK];
__device__ int   g_eslot[2][T_TOK];         // e*T_TOK + pos for each token's 2 experts
__device__ float g_ew[2][T_TOK];            // routing weights per token slot
__device__ float g_G [NEXP * T_TOK * FF];   // routed gate pre-act (compact rows)
__device__ float g_H [NEXP * T_TOK * FF];   // routed hidden silu(g)*u (compact rows)
__device__ float g_O [NEXP * T_TOK * DIM];  // routed expert outputs (compact rows)
__device__ float g_Gs[T_TOK * FSH];         // shared gate pre-act
__device__ float g_Hs[T_TOK * FSH];         // shared hidden

__device__ __forceinline__ float silu_f(float v) {
    return v / (1.f + __expf(-v));
}

__device__ __forceinline__ uint32_t f2tf32(float f) {
    uint32_t u;
    asm("cvt.rna.tf32.f32 %0, %1;" : "=r"(u) : "f"(f));
    return u;
}

__device__ __forceinline__ void mma_tf32(float4& c, const uint32_t a[4], const uint32_t b[2]) {
    asm volatile(
        "mma.sync.aligned.m16n8k8.row.col.f32.tf32.tf32.f32 "
        "{%0,%1,%2,%3}, {%4,%5,%6,%7}, {%8,%9}, {%0,%1,%2,%3};"
        : "+f"(c.x), "+f"(c.y), "+f"(c.z), "+f"(c.w)
        : "r"(a[0]), "r"(a[1]), "r"(a[2]), "r"(a[3]), "r"(b[0]), "r"(b[1]));
}

// ---------------- init ----------------
__global__ void k_init() {
    if (threadIdx.x < NEXP) g_count[threadIdx.x] = 0;
}

// ---------------- router (fp32 exact) ----------------
__global__ void k_router(const float* __restrict__ x, const float* __restrict__ Wr,
                         const float* __restrict__ bias) {
    int t    = blockIdx.x * blockDim.y + threadIdx.y;
    int lane = threadIdx.x;
    const float* xr = x + (size_t)t * DIM;
    float acc[NEXP];
#pragma unroll
    for (int e = 0; e < NEXP; e++) acc[e] = 0.f;
    for (int d = lane; d < DIM; d += 32) {
        float xv = xr[d];
        const float* w = Wr + d * NEXP;
#pragma unroll
        for (int e = 0; e < NEXP; e++) acc[e] += xv * w[e];
    }
#pragma unroll
    for (int o = 16; o > 0; o >>= 1)
#pragma unroll
        for (int e = 0; e < NEXP; e++)
            acc[e] += __shfl_down_sync(0xffffffffu, acc[e], o);
    if (lane == 0) {
        float v[NEXP];
#pragma unroll
        for (int e = 0; e < NEXP; e++) v[e] = acc[e] + bias[e];
        int i0 = 0;
#pragma unroll
        for (int e = 1; e < NEXP; e++) if (v[e] > v[i0]) i0 = e;
        int i1 = (i0 == 0) ? 1 : 0;
#pragma unroll
        for (int e = 0; e < NEXP; e++) if (e != i0 && v[e] > v[i1]) i1 = e;
        float e1    = __expf(v[i1] - v[i0]);
        float denom = 1.f + e1;
        float p0 = 1.f / denom, p1 = e1 / denom;
        int p = atomicAdd(&g_count[i0], 1);
        g_tok[i0][p] = t; g_eslot[0][t] = i0 * T_TOK + p; g_ew[0][t] = p0;
        p = atomicAdd(&g_count[i1], 1);
        g_tok[i1][p] = t; g_eslot[1][t] = i1 * T_TOK + p; g_ew[1][t] = p1;
    }
}

// =====================================================================
// tf32 tensor-core GEMM core, 2-stage double-buffered.
// 128x128 block tile, BK=16, 8 warps (64x32 warp tile each).
// A [M,K] row-major (optionally row-gathered), B [K,N] row-major.
// EPI 0: C[m,n] = acc
// EPI 1: C[m,n] = silu(Gprev[m,n]) * acc     (fused SwiGLU)
// =====================================================================
#define SPAD 136   // smem row stride in floats (pad -> conflict-free frag reads)

template<int EPI>
__device__ __forceinline__ void gemm_core(
    const float* __restrict__ Abase, const int* __restrict__ rowsA, int lda,
    const float* __restrict__ B, int ldb,
    float* __restrict__ C, int ldc,
    const float* __restrict__ Gprev,
    int Mcnt, int K)
{
    const int m0 = blockIdx.y * 128;
    if (m0 >= Mcnt) return;
    const int n0 = blockIdx.x * 128;

    __shared__ __align__(16) float As[2][16 * SPAD];
    __shared__ __align__(16) float Bs[2][16 * SPAD];

    const int tid  = threadIdx.x;
    const int lane = tid & 31;
    const int w    = tid >> 5;
    const int wm   = w >> 2;      // 0..1
    const int wn   = w & 3;       // 0..3

    // ---- A loader: thread covers row am, 8-wide k chunk aj ----
    const int am  = tid >> 1;
    const int aj  = tid & 1;
    const int amg = m0 + am;
    const bool aval = (amg < Mcnt);
    const float* Arow = Abase;
    if (aval) {
        int r = rowsA ? rowsA[amg] : amg;
        Arow = Abase + (size_t)r * lda + aj * 8;
    }
    // ---- B loader: thread covers k-row bk, 8 consecutive n ----
    const int bk  = tid >> 4;
    const int bnt = tid & 15;
    const float* Bptr = B + (size_t)bk * ldb + n0 + bnt * 8;
    const int bsoff = bk * SPAD + bnt * 8;
    float* AsT[2] = {&As[0][aj * 8 * SPAD + am], &As[1][aj * 8 * SPAD + am]};

    float4 acc[4][4];
#pragma unroll
    for (int i = 0; i < 4; i++)
#pragma unroll
        for (int j = 0; j < 4; j++) acc[i][j] = make_float4(0.f, 0.f, 0.f, 0.f);

    const int fk = lane & 3;
    const int fr = lane >> 2;
    const int nslab = K >> 4;

    uint32_t ra[8], rb[8];

    // ---- prologue: fetch + stage slab 0 into buffer 0 ----
    {
        float va[8] = {0,0,0,0,0,0,0,0};
        if (aval) {
            float4 t0 = *(const float4*)(Arow);
            float4 t1 = *(const float4*)(Arow + 4);
            va[0]=t0.x; va[1]=t0.y; va[2]=t0.z; va[3]=t0.w;
            va[4]=t1.x; va[5]=t1.y; va[6]=t1.z; va[7]=t1.w;
        }
        float4 t0 = *(const float4*)(Bptr);
        float4 t1 = *(const float4*)(Bptr + 4);
        float vb[8] = {t0.x,t0.y,t0.z,t0.w,t1.x,t1.y,t1.z,t1.w};
#pragma unroll
        for (int c = 0; c < 8; c++) { ra[c] = f2tf32(va[c]); rb[c] = f2tf32(vb[c]); }
#pragma unroll
        for (int c = 0; c < 8; c++) AsT[0][c * SPAD] = __uint_as_float(ra[c]);
        *(float4*)&Bs[0][bsoff]     = make_float4(__uint_as_float(rb[0]), __uint_as_float(rb[1]),
                                                  __uint_as_float(rb[2]), __uint_as_float(rb[3]));
        *(float4*)&Bs[0][bsoff + 4] = make_float4(__uint_as_float(rb[4]), __uint_as_float(rb[5]),
                                                  __uint_as_float(rb[6]), __uint_as_float(rb[7]));
    }
    __syncthreads();

    for (int it = 0; it < nslab; it++) {
        const int cur  = it & 1;
        const bool more = (it + 1 < nslab);

        // ---- prefetch slab it+1 into registers (overlaps compute) ----
        if (more) {
            const int k0 = (it + 1) * 16;
            float va[8] = {0,0,0,0,0,0,0,0};
            if (aval) {
                float4 t0 = *(const float4*)(Arow + k0);
                float4 t1 = *(const float4*)(Arow + k0 + 4);
                va[0]=t0.x; va[1]=t0.y; va[2]=t0.z; va[3]=t0.w;
                va[4]=t1.x; va[5]=t1.y; va[6]=t1.z; va[7]=t1.w;
            }
            float4 t0 = *(const float4*)(Bptr + (size_t)k0 * ldb);
            float4 t1 = *(const float4*)(Bptr + (size_t)k0 * ldb + 4);
            float vb[8] = {t0.x,t0.y,t0.z,t0.w,t1.x,t1.y,t1.z,t1.w};
#pragma unroll
            for (int c = 0; c < 8; c++) { ra[c] = f2tf32(va[c]); rb[c] = f2tf32(vb[c]); }
        }

        // ---- compute slab it from buffer cur ----
        const float* Ac = As[cur];
        const float* Bc = Bs[cur];
#pragma unroll
        for (int ks = 0; ks < 2; ks++) {
            const int kb = ks * 8 + fk;
            uint32_t a[4][4], b[4][2];
#pragma unroll
            for (int i = 0; i < 4; i++) {
                const int m = wm * 64 + i * 16 + fr;
                a[i][0] = __float_as_uint(Ac[kb * SPAD + m]);
                a[i][1] = __float_as_uint(Ac[kb * SPAD + m + 8]);
                a[i][2] = __float_as_uint(Ac[(kb + 4) * SPAD + m]);
                a[i][3] = __float_as_uint(Ac[(kb + 4) * SPAD + m + 8]);
            }
#pragma unroll
            for (int j = 0; j < 4; j++) {
                const int n = wn * 32 + j * 8 + fr;
                b[j][0] = __float_as_uint(Bc[kb * SPAD + n]);
                b[j][1] = __float_as_uint(Bc[(kb + 4) * SPAD + n]);
            }
#pragma unroll
            for (int i = 0; i < 4; i++)
#pragma unroll
                for (int j = 0; j < 4; j++)
                    mma_tf32(acc[i][j], a[i], b[j]);
        }

        // ---- stage slab it+1 into the other buffer ----
        if (more) {
            const int nxt = cur ^ 1;
#pragma unroll
            for (int c = 0; c < 8; c++) AsT[nxt][c * SPAD] = __uint_as_float(ra[c]);
            *(float4*)&Bs[nxt][bsoff]     = make_float4(__uint_as_float(rb[0]), __uint_as_float(rb[1]),
                                                        __uint_as_float(rb[2]), __uint_as_float(rb[3]));
            *(float4*)&Bs[nxt][bsoff + 4] = make_float4(__uint_as_float(rb[4]), __uint_as_float(rb[5]),
                                                        __uint_as_float(rb[6]), __uint_as_float(rb[7]));
        }
        __syncthreads();
    }

    // ---- epilogue ----
    const int er = lane >> 2;
    const int ec = (lane & 3) * 2;
#pragma unroll
    for (int i = 0; i < 4; i++) {
        const int mg0 = m0 + wm * 64 + i * 16 + er;
        const int mg1 = mg0 + 8;
#pragma unroll
        for (int j = 0; j < 4; j++) {
            const int n = n0 + wn * 32 + j * 8 + ec;
            if (EPI == 0) {
                if (mg0 < Mcnt)
                    *(float2*)&C[(size_t)mg0 * ldc + n] = make_float2(acc[i][j].x, acc[i][j].y);
                if (mg1 < Mcnt)
                    *(float2*)&C[(size_t)mg1 * ldc + n] = make_float2(acc[i][j].z, acc[i][j].w);
            } else {
                if (mg0 < Mcnt) {
                    float2 gp = *(const float2*)&Gprev[(size_t)mg0 * ldc + n];
                    *(float2*)&C[(size_t)mg0 * ldc + n] =
                        make_float2(silu_f(gp.x) * acc[i][j].x, silu_f(gp.y) * acc[i][j].y);
                }
                if (mg1 < Mcnt) {
                    float2 gp = *(const float2*)&Gprev[(size_t)mg1 * ldc + n];
                    *(float2*)&C[(size_t)mg1 * ldc + n] =
                        make_float2(silu_f(gp.x) * acc[i][j].z, silu_f(gp.y) * acc[i][j].w);
                }
            }
        }
    }
}

// ---------------- GEMM wrappers ----------------
__global__ __launch_bounds__(256, 2)
void k_sh_gate(const float* __restrict__ x, const float* __restrict__ Sg) {
    gemm_core<0>(x, nullptr, DIM, Sg, FSH, g_Gs, FSH, nullptr, T_TOK, DIM);
}

__global__ __launch_bounds__(256, 2)
void k_sh_up(const float* __restrict__ x, const float* __restrict__ Su) {
    gemm_core<1>(x, nullptr, DIM, Su, FSH, g_Hs, FSH, g_Gs, T_TOK, DIM);
}

__global__ __launch_bounds__(256, 2)
void k_sh_down(const float* __restrict__ Sd, float* __restrict__ out) {
    gemm_core<0>(g_Hs, nullptr, FSH, Sd, DIM, out, DIM, nullptr, T_TOK, FSH);
}

__global__ __launch_bounds__(256, 2)
void k_moe_gate(const float* __restrict__ x, const float* __restrict__ Wg) {
    const int e = blockIdx.z;
    gemm_core<0>(x, g_tok[e], DIM, Wg + (size_t)e * DIM * FF,
                 FF, g_G + (size_t)e * T_TOK * FF, FF, nullptr, g_count[e], DIM);
}

__global__ __launch_bounds__(256, 2)
void k_moe_up(const float* __restrict__ x, const float* __restrict__ Wu) {
    const int e = blockIdx.z;
    gemm_core<1>(x, g_tok[e], DIM, Wu + (size_t)e * DIM * FF,
                 FF, g_H + (size_t)e * T_TOK * FF, FF,
                 g_G + (size_t)e * T_TOK * FF, g_count[e], DIM);
}

__global__ __launch_bounds__(256, 2)
void k_moe_down(const float* __restrict__ Wd) {
    const int e = blockIdx.z;
    gemm_core<0>(g_H + (size_t)e * T_TOK * FF, nullptr, FF,
                 Wd + (size_t)e * FF * DIM, DIM,
                 g_O + (size_t)e * T_TOK * DIM, DIM, nullptr, g_count[e], FF);
}

// ---------------- final combine: out[t] += w0*O[s0] + w1*O[s1] ----------------
__global__ void k_combine(float* __restrict__ out) {
    const int t = blockIdx.x;
    const int i = threadIdx.x * 4;
    const int   s0 = g_eslot[0][t], s1 = g_eslot[1][t];
    const float w0 = g_ew[0][t],    w1 = g_ew[1][t];
    float4 o = *(float4*)&out[(size_t)t * DIM + i];
    float4 a = *(const float4*)&g_O[(size_t)s0 * DIM + i];
    float4 b = *(const float4*)&g_O[(size_t)s1 * DIM + i];
    o.x += w0 * a.x + w1 * b.x;
    o.y += w0 * a.y + w1 * b.y;
    o.z += w0 * a.z + w1 * b.z;
    o.w += w0 * a.w + w1 * b.w;
    *(float4*)&out[(size_t)t * DIM + i] = o;
}

// ---------------- launch ----------------
extern "C" void kernel_launch(void* const* d_in, const int* in_sizes, int n_in,
                              void* d_out, int out_size) {
    const float* x    = (const float*)d_in[0];
    const float* Wr   = (const float*)d_in[1];
    const float* Wg   = (const float*)d_in[2];
    const float* Wu   = (const float*)d_in[3];
    const float* Wd   = (const float*)d_in[4];
    const float* Sg   = (const float*)d_in[5];
    const float* Su   = (const float*)d_in[6];
    const float* Sd   = (const float*)d_in[7];
    const float* bias = (const float*)d_in[8];
    float* out = (float*)d_out;

    k_init<<<1, 32>>>();
    k_router<<<T_TOK / 8, dim3(32, 8)>>>(x, Wr, bias);

    // shared expert chain (down writes the full output buffer)
    k_sh_gate<<<dim3(FSH / 128, T_TOK / 128), 256>>>(x, Sg);
    k_sh_up  <<<dim3(FSH / 128, T_TOK / 128), 256>>>(x, Su);
    k_sh_down<<<dim3(DIM / 128, T_TOK / 128), 256>>>(Sd, out);

    // routed experts: sparse gather GEMMs -> compact outputs
    k_moe_gate<<<dim3(FF / 128, T_TOK / 128, NEXP), 256>>>(x, Wg);
    k_moe_up  <<<dim3(FF / 128, T_TOK / 128, NEXP), 256>>>(x, Wu);
    k_moe_down<<<dim3(DIM / 128, T_TOK / 128, NEXP), 256>>>(Wd);

    // combine routed outputs into shared-expert output
    k_combine<<<T_TOK, 256>>>(out);
}